// round 1
// baseline (speedup 1.0000x reference)
#include <cuda_runtime.h>

#define NB 512
#define NS 16384
#define NFFT 16384
#define HFFT 8192
#define NT 512

// Global accumulators: 0=pearson(1-r) sum, 1=cos sum, 2=nmi sum, 3=|xp-tp| sum, 4=tp sum
__device__ double g_acc[5];

__global__ void init_k() {
    if (threadIdx.x < 5) g_acc[threadIdx.x] = 0.0;
}

__device__ __forceinline__ int brev14(unsigned k) { return (int)(__brev(k) >> 18); }

struct Scr {
    double red[16];
    float  fred[16];
    int    hist[100];
    float  amaxv[16];
    int    amaxi[16];
};

__device__ double block_sum_d(double v, double* red, int tid) {
    __syncthreads();
    for (int o = 16; o; o >>= 1) v += __shfl_down_sync(0xffffffffu, v, o);
    if ((tid & 31) == 0) red[tid >> 5] = v;
    __syncthreads();
    if (tid == 0) {
        double w = red[0];
        for (int i = 1; i < 16; i++) w += red[i];
        red[0] = w;
    }
    __syncthreads();
    return red[0];
}

__device__ float block_min_f(float v, float* red, int tid) {
    __syncthreads();
    for (int o = 16; o; o >>= 1) v = fminf(v, __shfl_down_sync(0xffffffffu, v, o));
    if ((tid & 31) == 0) red[tid >> 5] = v;
    __syncthreads();
    if (tid == 0) {
        float w = red[0];
        for (int i = 1; i < 16; i++) w = fminf(w, red[i]);
        red[0] = w;
    }
    __syncthreads();
    return red[0];
}

__device__ float block_max_f(float v, float* red, int tid) {
    __syncthreads();
    for (int o = 16; o; o >>= 1) v = fmaxf(v, __shfl_down_sync(0xffffffffu, v, o));
    if ((tid & 31) == 0) red[tid >> 5] = v;
    __syncthreads();
    if (tid == 0) {
        float w = red[0];
        for (int i = 1; i < 16; i++) w = fmaxf(w, red[i]);
        red[0] = w;
    }
    __syncthreads();
    return red[0];
}

// Forward radix-2 DIF FFT (negative-exponent twiddles). Natural in -> bit-reversed out.
// tw[k] = exp(-i*pi*k/8192), k < 8192.
__device__ void fft_dif(float2* buf, const float2* tw, int tid) {
    for (int h = HFFT; h >= 1; h >>= 1) {
        int tstep = HFFT / h;
        for (int t = tid; t < HFFT; t += NT) {
            int j  = t & (h - 1);
            int i0 = ((t - j) << 1) + j;
            int i1 = i0 + h;
            float2 a = buf[i0], b = buf[i1];
            float2 w = tw[j * tstep];
            float2 s = make_float2(a.x - b.x, a.y - b.y);
            buf[i0] = make_float2(a.x + b.x, a.y + b.y);
            buf[i1] = make_float2(s.x * w.x - s.y * w.y, s.x * w.y + s.y * w.x);
        }
        __syncthreads();
    }
}

// Inverse radix-2 DIT FFT (positive-exponent twiddles = conj(tw)). Bit-reversed in -> natural out.
// Unnormalized (no 1/N) — fine for argmax.
__device__ void fft_dit_inv(float2* buf, const float2* tw, int tid) {
    for (int h = 1; h <= HFFT; h <<= 1) {
        int tstep = HFFT / h;
        for (int t = tid; t < HFFT; t += NT) {
            int j  = t & (h - 1);
            int i0 = ((t - j) << 1) + j;
            int i1 = i0 + h;
            float2 w  = tw[j * tstep];
            float2 bb = buf[i1];
            // bb * conj(w)
            float2 wb = make_float2(bb.x * w.x + bb.y * w.y, bb.y * w.x - bb.x * w.y);
            float2 a  = buf[i0];
            buf[i0] = make_float2(a.x + wb.x, a.y + wb.y);
            buf[i1] = make_float2(a.x - wb.x, a.y - wb.y);
        }
        __syncthreads();
    }
}

__global__ void __launch_bounds__(NT)
row_kernel(const float* __restrict__ pred, const float* __restrict__ targ,
           const int* __restrict__ ip) {
    extern __shared__ char smem[];
    float2* buf = (float2*)smem;                                   // 16384 * 8 = 131072 B
    float2* tw  = (float2*)(smem + (size_t)NFFT * sizeof(float2)); //  8192 * 8 =  65536 B
    Scr* scr = (Scr*)(smem + (size_t)NFFT * sizeof(float2) + (size_t)HFFT * sizeof(float2));

    const int tid = threadIdx.x;
    const int b   = blockIdx.x;
    const int ii  = *ip;
    const float* x = pred + (size_t)ii * NB * NS + (size_t)b * NS;
    const float* y = targ + (size_t)b * NS;

    // Twiddle table: tw[k] = exp(-i*pi*k/8192). k/8192 is exact in f32.
    for (int k = tid; k < HFFT; k += NT) {
        float s, c;
        sincospif((float)k * (1.0f / 8192.0f), &s, &c);
        tw[k] = make_float2(c, -s);
    }

    // ================= Phase 1: per-row stats (Pearson + min/max) =================
    double sx = 0, sy = 0, sxy = 0, sxx = 0, syy = 0;
    float xmn = 3.4e38f, xmx = -3.4e38f, ymn = 3.4e38f, ymx = -3.4e38f;
    for (int n = tid; n < NS; n += NT) {
        float xv = x[n], yv = y[n];
        sx += xv; sy += yv;
        sxy += (double)xv * yv;
        sxx += (double)xv * xv;
        syy += (double)yv * yv;
        xmn = fminf(xmn, xv); xmx = fmaxf(xmx, xv);
        ymn = fminf(ymn, yv); ymx = fmaxf(ymx, yv);
    }
    sx  = block_sum_d(sx,  scr->red, tid);
    sy  = block_sum_d(sy,  scr->red, tid);
    sxy = block_sum_d(sxy, scr->red, tid);
    sxx = block_sum_d(sxx, scr->red, tid);
    syy = block_sum_d(syy, scr->red, tid);
    xmn = block_min_f(xmn, scr->fred, tid);
    xmx = block_max_f(xmx, scr->fred, tid);
    ymn = block_min_f(ymn, scr->fred, tid);
    ymx = block_max_f(ymx, scr->fred, tid);

    if (tid == 0) {
        // Per-row Pearson is exactly invariant under the reference's global
        // standardization (uniform affine transform), so compute on raw data.
        const double N = (double)NS;
        double num = N * sxy - sx * sy;
        double den = sqrt((N * sxx - sx * sx) * (N * syy - sy * sy));
        atomicAdd(&g_acc[0], 1.0 - num / den);
    }

    // ================= Phase 2: mutual information =================
    for (int c = tid; c < 100; c += NT) scr->hist[c] = 0;
    __syncthreads();
    {
        float bwx = __fdiv_rn(xmx - xmn, 10.0f);
        float bwy = __fdiv_rn(ymx - ymn, 10.0f);
        for (int n = tid; n < NS; n += NT) {
            int ix = (int)__fdiv_rn(x[n] - xmn, bwx);  // trunc == astype(int32) for >=0
            int iy = (int)__fdiv_rn(y[n] - ymn, bwy);
            ix = min(max(ix, 0), 9);
            iy = min(max(iy, 0), 9);
            atomicAdd(&scr->hist[ix * 10 + iy], 1);
        }
    }
    __syncthreads();
    if (tid == 0) {
        const float denom = 8388608.0f;  // B*S — faithful to reference normalization
        float hx[10], hy[10];
        for (int k = 0; k < 10; k++) { hx[k] = 0.f; hy[k] = 0.f; }
        for (int a = 0; a < 10; a++)
            for (int c = 0; c < 10; c++) {
                float h = (float)scr->hist[a * 10 + c];
                hx[a] += h; hy[c] += h;
            }
        float mi = 0.f;
        for (int a = 0; a < 10; a++) {
            float px = hx[a] / denom;
            for (int c = 0; c < 10; c++) {
                float py  = hy[c] / denom;
                float pxy = (float)scr->hist[a * 10 + c] / denom;
                mi += pxy * logf((pxy + 1e-8f) / (px * py + 1e-8f));
            }
        }
        float hxe = 0.f, hye = 0.f;
        for (int k = 0; k < 10; k++) {
            hxe -= (hx[k] / denom) * logf(hx[k] / denom + 1e-8f);
            hye -= (hy[k] / denom) * logf(hy[k] / denom + 1e-8f);
        }
        float nmi = mi / ((hxe + hye) * 0.5f);
        atomicAdd(&g_acc[2], (double)nmi);
    }
    __syncthreads();

    // ================= Phase 3: phase correlation =================
    // One complex FFT of (x*w) + i*(t*w) gives both windowed real spectra.
    for (int n = tid; n < NFFT; n += NT) {
        float w = 0.5f * (1.0f - cospif((float)n * (1.0f / 8192.0f)));  // hann, periodic
        buf[n] = make_float2(x[n] * w, y[n] * w);
    }
    __syncthreads();
    fft_dif(buf, tw, tid);
    // Hermitian unpack (X = (Z+conj(Z_rev))/2, T = (Z-conj(Z_rev))/(2i)),
    // phase-only spectrum C = X*conj(T)/|.|, stored Hermitian-extended in bitrev order.
    for (int k = tid; k <= HFFT; k += NT) {
        int pk  = brev14((unsigned)k);
        int pnk = brev14((unsigned)((NFFT - k) & (NFFT - 1)));
        float2 Zk = buf[pk], Znk = buf[pnk];
        float Xr =  0.5f * (Zk.x + Znk.x), Xi = 0.5f * (Zk.y - Znk.y);
        float Tr =  0.5f * (Zk.y + Znk.y), Ti = -0.5f * (Zk.x - Znk.x);
        float Cr = Xr * Tr + Xi * Ti;   // X * conj(T)
        float Ci = Xi * Tr - Xr * Ti;
        float inv = rsqrtf(Cr * Cr + Ci * Ci);
        Cr *= inv; Ci *= inv;
        buf[pk]  = make_float2(Cr,  Ci);
        buf[pnk] = make_float2(Cr, -Ci);   // conj for k and N-k (same slot when k==0/8192)
    }
    __syncthreads();
    fft_dit_inv(buf, tw, tid);
    {
        // argmax over real part, first-occurrence tie semantics
        float bv = -3.4e38f; int bi = 0;
        for (int n = tid; n < NFFT; n += NT) {
            float v = buf[n].x;
            if (v > bv) { bv = v; bi = n; }
        }
        for (int o = 16; o; o >>= 1) {
            float ov = __shfl_down_sync(0xffffffffu, bv, o);
            int   oi = __shfl_down_sync(0xffffffffu, bi, o);
            if (ov > bv || (ov == bv && oi < bi)) { bv = ov; bi = oi; }
        }
        if ((tid & 31) == 0) { scr->amaxv[tid >> 5] = bv; scr->amaxi[tid >> 5] = bi; }
        __syncthreads();
        if (tid == 0) {
            for (int w2 = 1; w2 < 16; w2++) {
                float ov = scr->amaxv[w2]; int oi = scr->amaxi[w2];
                if (ov > bv || (ov == bv && oi < bi)) { bv = ov; bi = oi; }
            }
            atomicAdd(&g_acc[1], (double)cospif((float)bi * (1.0f / 8192.0f)));
        }
        __syncthreads();
    }

    // ================= Phase 4: power spectrum =================
    for (int n = tid; n < NFFT; n += NT)
        buf[n] = make_float2(x[n], y[n]);
    __syncthreads();
    fft_dif(buf, tw, tid);
    {
        double pa = 0.0, pt = 0.0;
        for (int k = tid; k <= HFFT; k += NT) {
            int pk  = brev14((unsigned)k);
            int pnk = brev14((unsigned)((NFFT - k) & (NFFT - 1)));
            float2 Zk = buf[pk], Znk = buf[pnk];
            float Xr =  0.5f * (Zk.x + Znk.x), Xi = 0.5f * (Zk.y - Znk.y);
            float Tr =  0.5f * (Zk.y + Znk.y), Ti = -0.5f * (Zk.x - Znk.x);
            float xp = Xr * Xr + Xi * Xi;
            float tp = Tr * Tr + Ti * Ti;
            pa += (double)fabsf(xp - tp);
            pt += (double)tp;
        }
        pa = block_sum_d(pa, scr->red, tid);
        pt = block_sum_d(pt, scr->red, tid);
        if (tid == 0) {
            atomicAdd(&g_acc[3], pa);
            atomicAdd(&g_acc[4], pt);
        }
    }
}

__global__ void fin_k(const int* __restrict__ ep, float* __restrict__ out) {
    int e = *ep;
    double loss = g_acc[0] / (double)NB;
    if (e >= 400) {
        loss += 1.0 - g_acc[1] / (double)NB;   // phase correlation term
        loss += g_acc[3] / g_acc[4];           // power spectrum: means over same count cancel
    }
    if (e >= 700) {
        loss += 1.0 - g_acc[2] / (double)NB;   // mutual information term
    }
    out[0] = (float)loss;
}

extern "C" void kernel_launch(void* const* d_in, const int* in_sizes, int n_in,
                              void* d_out, int out_size) {
    const float* pred = (const float*)d_in[0];
    const float* targ = (const float*)d_in[1];
    const int*   ip   = (const int*)d_in[2];
    const int*   ep   = (const int*)d_in[3];
    float* out = (float*)d_out;

    size_t smem = (size_t)NFFT * sizeof(float2) + (size_t)HFFT * sizeof(float2) + sizeof(Scr);
    cudaFuncSetAttribute(row_kernel, cudaFuncAttributeMaxDynamicSharedMemorySize, (int)smem);

    init_k<<<1, 32>>>();
    row_kernel<<<NB, NT, smem>>>(pred, targ, ip);
    fin_k<<<1, 1>>>(ep, out);
}

// round 2
// speedup vs baseline: 2.3939x; 2.3939x over previous
#include <cuda_runtime.h>

#define NB 512
#define NS 16384
#define NFFT 16384
#define HFFT 8192
#define NT 512
#define SBUF_N 16896
#define SKEW(k) ((k) + ((k) >> 5))

// Global accumulators: 0=pearson(1-r) sum, 1=cos sum, 2=nmi sum, 3=|xp-tp| sum, 4=tp sum
__device__ double g_acc[5];

__global__ void init_k() {
    if (threadIdx.x < 5) g_acc[threadIdx.x] = 0.0;
}

struct Scr {
    double red[16];
    float  fred[16];
    int    hist[100];
    float  amaxv[16];
    int    amaxi[16];
};

// ---------------- small helpers ----------------
__device__ __forceinline__ float2 cmul(float2 a, float2 b) {
    return make_float2(a.x * b.x - a.y * b.y, a.x * b.y + a.y * b.x);
}

__device__ __forceinline__ int BR5(int x) {
    return ((x & 1) << 4) | ((x & 2) << 2) | (x & 4) | ((x & 8) >> 2) | ((x & 16) >> 4);
}
__device__ __forceinline__ int BR4(int x) {
    return ((x & 1) << 3) | ((x & 2) << 1) | ((x & 4) >> 1) | ((x & 8) >> 3);
}

// twiddle constants exp(-i*pi*e/16); switch form so fully-unrolled call sites fold to immediates
__device__ __forceinline__ float twc(int e) {
    switch (e & 15) {
        case 0:  return  1.0f;
        case 1:  return  0.980785280403f;
        case 2:  return  0.923879532511f;
        case 3:  return  0.831469612303f;
        case 4:  return  0.707106781187f;
        case 5:  return  0.555570233020f;
        case 6:  return  0.382683432365f;
        case 7:  return  0.195090322016f;
        case 8:  return  0.0f;
        case 9:  return -0.195090322016f;
        case 10: return -0.382683432365f;
        case 11: return -0.555570233020f;
        case 12: return -0.707106781187f;
        case 13: return -0.831469612303f;
        case 14: return -0.923879532511f;
        default: return -0.980785280403f;
    }
}
__device__ __forceinline__ float tws(int e) {
    switch (e & 15) {
        case 0:  return  0.0f;
        case 1:  return -0.195090322016f;
        case 2:  return -0.382683432365f;
        case 3:  return -0.555570233020f;
        case 4:  return -0.707106781187f;
        case 5:  return -0.831469612303f;
        case 6:  return -0.923879532511f;
        case 7:  return -0.980785280403f;
        case 8:  return -1.0f;
        case 9:  return -0.980785280403f;
        case 10: return -0.923879532511f;
        case 11: return -0.831469612303f;
        case 12: return -0.707106781187f;
        case 13: return -0.555570233020f;
        case 14: return -0.382683432365f;
        default: return -0.195090322016f;
    }
}

__device__ __forceinline__ void bfly(float2& p, float2& q, int e) {
    float c = twc(e), s = tws(e);
    float ax = p.x, ay = p.y, bx = q.x, by = q.y;
    p.x = ax + bx; p.y = ay + by;
    float dx = ax - bx, dy = ay - by;
    q.x = dx * c - dy * s;
    q.y = dx * s + dy * c;
}

// DIF radix-2 FFT of 32 register-resident points. Output at position q = frequency brev5(q).
__device__ __forceinline__ void fft32(float2* v) {
#pragma unroll
    for (int h = 16; h >= 1; h >>= 1) {
#pragma unroll
        for (int g = 0; g < 32; g += 2 * h) {
#pragma unroll
            for (int j = 0; j < h; j++) {
                bfly(v[g + j], v[g + j + h], j * (16 / h));
            }
        }
    }
}

// DIF radix-2 FFT of 16 points. Output position q = frequency brev4(q).
__device__ __forceinline__ void fft16(float2* v) {
#pragma unroll
    for (int h = 8; h >= 1; h >>= 1) {
#pragma unroll
        for (int g = 0; g < 16; g += 2 * h) {
#pragma unroll
            for (int j = 0; j < h; j++) {
                bfly(v[g + j], v[g + j + h], j * (16 / h));
            }
        }
    }
}

// ---------------- 16384-pt FFT, 3 passes (32 x 32 x 16), 512 threads ----------------
// On entry: v[r] = input[tid + 512*r] (natural order).
// SCATTER=true : results written to sbuf[SKEW(k)] in natural frequency order.
// SCATTER=false: per-thread argmax of Re(X[k]) returned in (*bvp, *bip), min-index ties.
template <bool SCATTER>
__device__ __forceinline__ void fft16k(float2 (&v)[32], float2* __restrict__ sbuf, int tid,
                                       float* bvp, int* bip)
{
    __syncthreads();   // prior sbuf readers done before pass-1 stores

    // ---- pass 1: DFT_32 over stride-512, twiddle W_N^{t*j}, store [j][m] ----
    fft32(v);
    {
        float sp, cp;
        sincospif((float)tid * (1.0f / 8192.0f), &sp, &cp);
        float2 step = make_float2(cp, -sp);
        float2 w = make_float2(1.0f, 0.0f);
#pragma unroll
        for (int j = 0; j < 32; j++) {
            sbuf[j * 512 + tid] = cmul(v[BR5(j)], w);
            w = cmul(w, step);
        }
    }
    __syncthreads();

    // ---- pass 2: within each 512-block, DFT_32 over stride-16, twiddle W_512^{m2*j2} ----
    {
        int j = tid >> 4, m2 = tid & 15;
        int base = j * 512 + m2;
#pragma unroll
        for (int r2 = 0; r2 < 32; r2++) v[r2] = sbuf[base + 16 * r2];
        __syncthreads();
        fft32(v);
        float sp, cp;
        sincospif((float)m2 * (1.0f / 256.0f), &sp, &cp);
        float2 step = make_float2(cp, -sp);
        float2 w = make_float2(1.0f, 0.0f);
        int pbase = j * 32;
#pragma unroll
        for (int j2 = 0; j2 < 32; j2++) {
            sbuf[(pbase + j2) * 16 + (m2 ^ (j2 & 15))] = cmul(v[BR5(j2)], w);
            w = cmul(w, step);
        }
    }
    __syncthreads();

    // ---- pass 3: two 16-pt FFTs per thread (pairs p = tid, tid+512) ----
#pragma unroll
    for (int c = 0; c < 2; c++) {
        int p = tid + c * 512;
        int sw = p & 15;
#pragma unroll
        for (int m2 = 0; m2 < 16; m2++) v[c * 16 + m2] = sbuf[p * 16 + (m2 ^ sw)];
    }
    __syncthreads();
    fft16(v);
    fft16(v + 16);

    if (SCATTER) {
#pragma unroll
        for (int c = 0; c < 2; c++) {
            int p = tid + c * 512;
            int kb = (p >> 5) + 32 * (p & 31);
#pragma unroll
            for (int q = 0; q < 16; q++) {
                int k = kb + 1024 * BR4(q);
                sbuf[SKEW(k)] = v[c * 16 + q];
            }
        }
        __syncthreads();
    } else {
        float bv = -3.4e38f; int bi = 0;
#pragma unroll
        for (int c = 0; c < 2; c++) {
            int p = tid + c * 512;
            int kb = (p >> 5) + 32 * (p & 31);
#pragma unroll
            for (int q = 0; q < 16; q++) {
                int k = kb + 1024 * BR4(q);
                float re = v[c * 16 + q].x;
                if (re > bv || (re == bv && k < bi)) { bv = re; bi = k; }
            }
        }
        *bvp = bv; *bip = bi;
    }
}

// ---------------- block reductions ----------------
__device__ double block_sum_d(double v, double* red, int tid) {
    __syncthreads();
    for (int o = 16; o; o >>= 1) v += __shfl_down_sync(0xffffffffu, v, o);
    if ((tid & 31) == 0) red[tid >> 5] = v;
    __syncthreads();
    if (tid == 0) {
        double w = red[0];
        for (int i = 1; i < 16; i++) w += red[i];
        red[0] = w;
    }
    __syncthreads();
    return red[0];
}

__device__ float block_min_f(float v, float* red, int tid) {
    __syncthreads();
    for (int o = 16; o; o >>= 1) v = fminf(v, __shfl_down_sync(0xffffffffu, v, o));
    if ((tid & 31) == 0) red[tid >> 5] = v;
    __syncthreads();
    if (tid == 0) {
        float w = red[0];
        for (int i = 1; i < 16; i++) w = fminf(w, red[i]);
        red[0] = w;
    }
    __syncthreads();
    return red[0];
}

__device__ float block_max_f(float v, float* red, int tid) {
    __syncthreads();
    for (int o = 16; o; o >>= 1) v = fmaxf(v, __shfl_down_sync(0xffffffffu, v, o));
    if ((tid & 31) == 0) red[tid >> 5] = v;
    __syncthreads();
    if (tid == 0) {
        float w = red[0];
        for (int i = 1; i < 16; i++) w = fmaxf(w, red[i]);
        red[0] = w;
    }
    __syncthreads();
    return red[0];
}

// ---------------- main per-row kernel ----------------
__global__ void __launch_bounds__(NT, 1)
row_kernel(const float* __restrict__ pred, const float* __restrict__ targ,
           const int* __restrict__ ip)
{
    extern __shared__ char smem[];
    float2* sbuf = (float2*)smem;
    Scr* scr = (Scr*)(smem + (size_t)SBUF_N * sizeof(float2));

    const int tid = threadIdx.x;
    const int b   = blockIdx.x;
    const int ii  = *ip;
    const float* x = pred + (size_t)ii * NB * NS + (size_t)b * NS;
    const float* y = targ + (size_t)b * NS;

    // ================= Phase 1: Pearson stats + min/max =================
    double sx = 0, sy = 0, sxy = 0, sxx = 0, syy = 0;
    float xmn = 3.4e38f, xmx = -3.4e38f, ymn = 3.4e38f, ymx = -3.4e38f;
    for (int n = tid; n < NS; n += NT) {
        float xv = x[n], yv = y[n];
        sx += xv; sy += yv;
        sxy += (double)xv * yv;
        sxx += (double)xv * xv;
        syy += (double)yv * yv;
        xmn = fminf(xmn, xv); xmx = fmaxf(xmx, xv);
        ymn = fminf(ymn, yv); ymx = fmaxf(ymx, yv);
    }
    sx  = block_sum_d(sx,  scr->red, tid);
    sy  = block_sum_d(sy,  scr->red, tid);
    sxy = block_sum_d(sxy, scr->red, tid);
    sxx = block_sum_d(sxx, scr->red, tid);
    syy = block_sum_d(syy, scr->red, tid);
    xmn = block_min_f(xmn, scr->fred, tid);
    xmx = block_max_f(xmx, scr->fred, tid);
    ymn = block_min_f(ymn, scr->fred, tid);
    ymx = block_max_f(ymx, scr->fred, tid);

    if (tid == 0) {
        // Per-row Pearson is invariant under the reference's global standardization.
        const double N = (double)NS;
        double num = N * sxy - sx * sy;
        double den = sqrt((N * sxx - sx * sx) * (N * syy - sy * sy));
        atomicAdd(&g_acc[0], 1.0 - num / den);
    }

    // ================= Phase 2: mutual information =================
    for (int c = tid; c < 100; c += NT) scr->hist[c] = 0;
    __syncthreads();
    {
        float bwx = __fdiv_rn(xmx - xmn, 10.0f);
        float bwy = __fdiv_rn(ymx - ymn, 10.0f);
        for (int n = tid; n < NS; n += NT) {
            int ix = (int)__fdiv_rn(x[n] - xmn, bwx);
            int iy = (int)__fdiv_rn(y[n] - ymn, bwy);
            ix = min(max(ix, 0), 9);
            iy = min(max(iy, 0), 9);
            atomicAdd(&scr->hist[ix * 10 + iy], 1);
        }
    }
    __syncthreads();
    if (tid == 0) {
        const float denom = 8388608.0f;  // B*S — faithful to reference normalization
        float hx[10], hy[10];
        for (int k = 0; k < 10; k++) { hx[k] = 0.f; hy[k] = 0.f; }
        for (int a = 0; a < 10; a++)
            for (int c = 0; c < 10; c++) {
                float h = (float)scr->hist[a * 10 + c];
                hx[a] += h; hy[c] += h;
            }
        float mi = 0.f;
        for (int a = 0; a < 10; a++) {
            float px = hx[a] / denom;
            for (int c = 0; c < 10; c++) {
                float py  = hy[c] / denom;
                float pxy = (float)scr->hist[a * 10 + c] / denom;
                mi += pxy * logf((pxy + 1e-8f) / (px * py + 1e-8f));
            }
        }
        float hxe = 0.f, hye = 0.f;
        for (int k = 0; k < 10; k++) {
            hxe -= (hx[k] / denom) * logf(hx[k] / denom + 1e-8f);
            hye -= (hy[k] / denom) * logf(hy[k] / denom + 1e-8f);
        }
        float nmi = mi / ((hxe + hye) * 0.5f);
        atomicAdd(&g_acc[2], (double)nmi);
    }

    // ================= Phase 3: phase correlation =================
    float2 v[32];
#pragma unroll
    for (int r = 0; r < 32; r++) {
        int n = tid + 512 * r;
        float w = 0.5f - 0.5f * cospif((float)n * (1.0f / 8192.0f));  // periodic hann
        v[r] = make_float2(x[n] * w, y[n] * w);
    }
    float bv; int bi;
    fft16k<true>(v, sbuf, tid, &bv, &bi);   // Z = FFT(x*w + i*y*w), natural order in sbuf

    // Hermitian unpack -> phase-only spectrum C; store D = conj(C) (full extension) in place.
    for (int k = tid; k <= HFFT; k += NT) {
        int ak  = SKEW(k);
        int ank = SKEW((NFFT - k) & (NFFT - 1));
        float2 Zk = sbuf[ak], Znk = sbuf[ank];
        float Xr =  0.5f * (Zk.x + Znk.x), Xi = 0.5f * (Zk.y - Znk.y);
        float Tr =  0.5f * (Zk.y + Znk.y), Ti = -0.5f * (Zk.x - Znk.x);
        float Cr = Xr * Tr + Xi * Ti;   // X * conj(T)
        float Ci = Xi * Tr - Xr * Ti;
        float inv = rsqrtf(Cr * Cr + Ci * Ci);
        Cr *= inv; Ci *= inv;
        sbuf[ak]  = make_float2(Cr, -Ci);   // conj(C[k])
        sbuf[ank] = make_float2(Cr,  Ci);   // conj(C[N-k]) = C[k]
    }
    __syncthreads();

    // Inverse FFT via forward FFT of conj: Re(FFT(conj C)[n]) = N * Re(ifft(C)[n]).
#pragma unroll
    for (int r = 0; r < 32; r++) v[r] = sbuf[SKEW(tid + 512 * r)];
    fft16k<false>(v, sbuf, tid, &bv, &bi);

    // block argmax (value, min index)
    for (int o = 16; o; o >>= 1) {
        float ov = __shfl_down_sync(0xffffffffu, bv, o);
        int   oi = __shfl_down_sync(0xffffffffu, bi, o);
        if (ov > bv || (ov == bv && oi < bi)) { bv = ov; bi = oi; }
    }
    if ((tid & 31) == 0) { scr->amaxv[tid >> 5] = bv; scr->amaxi[tid >> 5] = bi; }
    __syncthreads();
    if (tid == 0) {
        for (int w2 = 1; w2 < 16; w2++) {
            float ov = scr->amaxv[w2]; int oi = scr->amaxi[w2];
            if (ov > bv || (ov == bv && oi < bi)) { bv = ov; bi = oi; }
        }
        atomicAdd(&g_acc[1], (double)cospif((float)bi * (1.0f / 8192.0f)));
    }

    // ================= Phase 4: power spectrum =================
#pragma unroll
    for (int r = 0; r < 32; r++) {
        int n = tid + 512 * r;
        v[r] = make_float2(x[n], y[n]);
    }
    fft16k<true>(v, sbuf, tid, &bv, &bi);   // leading sync inside covers scr/sbuf hazards

    {
        double pa = 0.0, pt = 0.0;
        for (int k = tid; k <= HFFT; k += NT) {
            int ak  = SKEW(k);
            int ank = SKEW((NFFT - k) & (NFFT - 1));
            float2 Zk = sbuf[ak], Znk = sbuf[ank];
            float Xr =  0.5f * (Zk.x + Znk.x), Xi = 0.5f * (Zk.y - Znk.y);
            float Tr =  0.5f * (Zk.y + Znk.y), Ti = -0.5f * (Zk.x - Znk.x);
            float xp = Xr * Xr + Xi * Xi;
            float tp = Tr * Tr + Ti * Ti;
            pa += (double)fabsf(xp - tp);
            pt += (double)tp;
        }
        pa = block_sum_d(pa, scr->red, tid);
        pt = block_sum_d(pt, scr->red, tid);
        if (tid == 0) {
            atomicAdd(&g_acc[3], pa);
            atomicAdd(&g_acc[4], pt);
        }
    }
}

__global__ void fin_k(const int* __restrict__ ep, float* __restrict__ out) {
    int e = *ep;
    double loss = g_acc[0] / (double)NB;
    if (e >= 400) {
        loss += 1.0 - g_acc[1] / (double)NB;   // phase correlation term
        loss += g_acc[3] / g_acc[4];           // power spectrum (means over same count cancel)
    }
    if (e >= 700) {
        loss += 1.0 - g_acc[2] / (double)NB;   // mutual information term
    }
    out[0] = (float)loss;
}

extern "C" void kernel_launch(void* const* d_in, const int* in_sizes, int n_in,
                              void* d_out, int out_size) {
    const float* pred = (const float*)d_in[0];
    const float* targ = (const float*)d_in[1];
    const int*   ip   = (const int*)d_in[2];
    const int*   ep   = (const int*)d_in[3];
    float* out = (float*)d_out;

    size_t smem = (size_t)SBUF_N * sizeof(float2) + sizeof(Scr);
    cudaFuncSetAttribute(row_kernel, cudaFuncAttributeMaxDynamicSharedMemorySize, (int)smem);

    init_k<<<1, 32>>>();
    row_kernel<<<NB, NT, smem>>>(pred, targ, ip);
    fin_k<<<1, 1>>>(ep, out);
}